// round 3
// baseline (speedup 1.0000x reference)
#include <cuda_runtime.h>
#include <math.h>

typedef long long ll;
#define DI __device__ __forceinline__

constexpr int Bc=4, Sc=1024, Dc=1024, Hc=16, DHc=64, Ec=8, FFc=4096;
constexpr int TOK = Bc*Sc;                 // 4096
constexpr ll TD   = (ll)TOK*Dc;            // 4,194,304 elems (16MB)
constexpr ll SC_SZ= (ll)Bc*Hc*Sc*Sc;       // 67,108,864 elems (256MB)

// ---- phase-overlapped scratch pool (640MB) + persistents (2x16MB) ----
// Phase A (attention): [xn | q | k | v | ao | scores]  = 5*TD + SC_SZ = 336MB
// Phase B (MoE):       [h (512MB) | eo (128MB)]        = 640MB
constexpr ll POOL_ELEMS = (ll)Ec*4096*FFc + (ll)Ec*4096*Dc;   // 167,772,160
__device__ float g_pool[POOL_ELEMS];
__device__ float g_x1 [TD];
__device__ float g_xn2[TD];
__device__ float g_logits[TOK*Ec];
__device__ float g_wgt[TOK*2];
__device__ int   g_cnt[Ec];
__device__ int   g_etok[Ec*4096];
__device__ int   g_slot[TOK*2];

DI float to_tf32(float x){ unsigned u; asm("cvt.rna.tf32.f32 %0, %1;":"=r"(u):"f"(x)); return __uint_as_float(u); }

DI void mma_tf32(float* c, const unsigned* a, const unsigned* b){
    asm volatile("mma.sync.aligned.m16n8k8.row.col.f32.tf32.tf32.f32 "
        "{%0,%1,%2,%3}, {%4,%5,%6,%7}, {%8,%9}, {%0,%1,%2,%3};"
        : "+f"(c[0]),"+f"(c[1]),"+f"(c[2]),"+f"(c[3])
        : "r"(a[0]),"r"(a[1]),"r"(a[2]),"r"(a[3]),"r"(b[0]),"r"(b[1]));
}

DI float gelu_exact(float x){ return 0.5f*x*(1.0f+erff(x*0.70710678118654752440f)); }

// C[z] = epi(A[z]@B[z]*scale + bias, residual)
// BLAYOUT 0: B is [K,N] row-major. 1: B is [N,K] row-major (B^T).
// EPI 1: GELU epilogue. GATHER: A rows from per-z gather list. counts bounds M.
template <int BN, int BLAYOUT, int EPI, bool GATHER>
__global__ void __launch_bounds__(256) gemm_tf32(
    const float* __restrict__ A, int lda, ll sAb, ll sAh,
    const float* __restrict__ B, int ldb, ll sBb, ll sBh,
    float* __restrict__ C, int ldc, ll sCb, ll sCh,
    const float* __restrict__ bias, ll biasStride,
    const float* __restrict__ residual, float scale,
    int M, int N, int K, int nH,
    const int* __restrict__ gather, const int* __restrict__ counts)
{
    constexpr int BM=128, BK=16;
    constexpr int LDA_S = BK+4;
    constexpr int LDB_S = (BLAYOUT==0) ? (BN+8) : (BK+4);
    constexpr int B_ELEMS = (BLAYOUT==0) ? (BK*LDB_S) : (BN*LDB_S);
    constexpr int HALF_BN = BN/2;
    constexpr int NI = HALF_BN/8;
    constexpr int BIT = BN/64;

    __shared__ float As[BM*LDA_S];
    __shared__ float Bs[B_ELEMS];

    const int z = blockIdx.z;
    const int bb = z/nH, hh = z%nH;
    const float* Ab = A + bb*sAb + hh*sAh;
    const float* Bp = B + bb*sBb + hh*sBh;

    const int Meff = counts ? counts[z] : M;
    const int m0 = blockIdx.y*BM;
    if (m0 >= Meff) return;
    const int n0 = blockIdx.x*BN;

    const int tid = threadIdx.x;
    const int lane = tid&31, warp = tid>>5;
    const int wm = warp&3, wn = warp>>2;

    const int* grows = GATHER ? (gather + z*4096) : nullptr;

    ll arow[2]; int asr[2], asc[2];
#pragma unroll
    for (int it=0; it<2; it++){
        int idx = tid + it*256;
        int r = idx>>2, c4 = (idx&3)*4;
        int m = m0 + r;
        ll srow;
        if (GATHER){ int mm = (m < Meff) ? m : (Meff-1); srow = grows[mm]; }
        else srow = m;
        arow[it] = srow*(ll)lda; asr[it]=r; asc[it]=c4;
    }

    float acc[2][NI][4];
#pragma unroll
    for (int mi=0;mi<2;mi++)
#pragma unroll
    for (int ni=0;ni<NI;ni++)
#pragma unroll
    for (int j=0;j<4;j++) acc[mi][ni][j]=0.0f;

    const int r0 = lane>>2, cc = lane&3;

    for (int k0=0; k0<K; k0+=BK){
#pragma unroll
        for (int it=0; it<2; it++){
            float4 vv = *(const float4*)(Ab + arow[it] + k0 + asc[it]);
            vv.x=to_tf32(vv.x); vv.y=to_tf32(vv.y); vv.z=to_tf32(vv.z); vv.w=to_tf32(vv.w);
            *(float4*)(As + asr[it]*LDA_S + asc[it]) = vv;
        }
#pragma unroll
        for (int it=0; it<BIT; it++){
            int idx = tid + it*256;
            int r, c4;
            if (BLAYOUT==0){ r = idx/(BN/4); c4 = (idx%(BN/4))*4; }
            else           { r = idx>>2;     c4 = (idx&3)*4; }
            float4 vv;
            if (BLAYOUT==0) vv = *(const float4*)(Bp + (ll)(k0+r)*ldb + n0 + c4);
            else            vv = *(const float4*)(Bp + (ll)(n0+r)*ldb + k0 + c4);
            vv.x=to_tf32(vv.x); vv.y=to_tf32(vv.y); vv.z=to_tf32(vv.z); vv.w=to_tf32(vv.w);
            *(float4*)(Bs + r*LDB_S + c4) = vv;
        }
        __syncthreads();

#pragma unroll
        for (int kk=0; kk<BK; kk+=8){
            unsigned a[2][4], b[NI][2];
#pragma unroll
            for (int mi=0;mi<2;mi++){
                int rb = wm*32 + mi*16;
                a[mi][0]=__float_as_uint(As[(rb+r0  )*LDA_S + kk+cc  ]);
                a[mi][1]=__float_as_uint(As[(rb+r0+8)*LDA_S + kk+cc  ]);
                a[mi][2]=__float_as_uint(As[(rb+r0  )*LDA_S + kk+cc+4]);
                a[mi][3]=__float_as_uint(As[(rb+r0+8)*LDA_S + kk+cc+4]);
            }
#pragma unroll
            for (int ni=0;ni<NI;ni++){
                int nb = wn*HALF_BN + ni*8 + r0;
                if (BLAYOUT==0){
                    b[ni][0]=__float_as_uint(Bs[(kk+cc  )*LDB_S + nb]);
                    b[ni][1]=__float_as_uint(Bs[(kk+cc+4)*LDB_S + nb]);
                } else {
                    b[ni][0]=__float_as_uint(Bs[nb*LDB_S + kk+cc  ]);
                    b[ni][1]=__float_as_uint(Bs[nb*LDB_S + kk+cc+4]);
                }
            }
#pragma unroll
            for (int mi=0;mi<2;mi++)
#pragma unroll
            for (int ni=0;ni<NI;ni++)
                mma_tf32(acc[mi][ni], a[mi], b[ni]);
        }
        __syncthreads();
    }

    const float* biasP = bias ? (bias + z*biasStride) : nullptr;
    float* Cp = C + bb*sCb + hh*sCh;
    const float* resP = residual ? (residual + bb*sCb + hh*sCh) : nullptr;
    const int c0 = (lane&3)*2;

#pragma unroll
    for (int mi=0;mi<2;mi++)
#pragma unroll
    for (int ni=0;ni<NI;ni++)
#pragma unroll
    for (int half=0; half<2; half++){
        int row = m0 + wm*32 + mi*16 + r0 + half*8;
        int col = n0 + wn*HALF_BN + ni*8 + c0;
        float v0 = acc[mi][ni][half*2+0]*scale;
        float v1 = acc[mi][ni][half*2+1]*scale;
        if (biasP){ v0 += biasP[col]; v1 += biasP[col+1]; }
        if (EPI==1){ v0 = gelu_exact(v0); v1 = gelu_exact(v1); }
        ll ci = (ll)row*ldc + col;
        if (resP){ v0 += resP[ci]; v1 += resP[ci+1]; }
        Cp[ci]=v0; Cp[ci+1]=v1;
    }
}

__global__ void __launch_bounds__(256) ln_kernel(
    const float* __restrict__ x, const float* __restrict__ g,
    const float* __restrict__ bet, float* __restrict__ o)
{
    int row = blockIdx.x;
    const float* xr = x + (ll)row*Dc;
    float* orow = o + (ll)row*Dc;
    int tid = threadIdx.x;
    float vv[4], s=0.f, s2=0.f;
#pragma unroll
    for (int i=0;i<4;i++){ float t = xr[tid+i*256]; vv[i]=t; s+=t; s2+=t*t; }
    int lane=tid&31, w=tid>>5;
#pragma unroll
    for (int off=16; off; off>>=1){
        s  += __shfl_xor_sync(0xffffffffu, s,  off);
        s2 += __shfl_xor_sync(0xffffffffu, s2, off);
    }
    __shared__ float rs[8], rs2[8], fmu, frs;
    if (lane==0){ rs[w]=s; rs2[w]=s2; }
    __syncthreads();
    if (tid==0){
        float a=0.f, b2=0.f;
#pragma unroll
        for (int j=0;j<8;j++){ a+=rs[j]; b2+=rs2[j]; }
        float mu = a*(1.0f/Dc);
        float var = b2*(1.0f/Dc) - mu*mu;
        fmu=mu; frs=rsqrtf(var + 1e-5f);
    }
    __syncthreads();
    float mu=fmu, rstd=frs;
#pragma unroll
    for (int i=0;i<4;i++){ int c=tid+i*256; orow[c] = (vv[i]-mu)*rstd*g[c] + bet[c]; }
}

__global__ void __launch_bounds__(256) softmax_kernel(
    float* __restrict__ sc, const int* __restrict__ mask)
{
    ll row = blockIdx.x;
    int b = (int)(row >> 14);
    float* sr = sc + row*(ll)Sc;
    const int* mr = mask + (ll)b*Sc;
    int tid=threadIdx.x, lane=tid&31, w=tid>>5;
    float vv[4], mx = -1e30f;
#pragma unroll
    for (int i=0;i<4;i++){
        int c = tid+i*256;
        float val = (mr[c]!=0) ? sr[c] : -1e30f;
        vv[i]=val; mx=fmaxf(mx,val);
    }
#pragma unroll
    for (int off=16; off; off>>=1) mx = fmaxf(mx, __shfl_xor_sync(0xffffffffu, mx, off));
    __shared__ float sm[8], smx, ss[8], ssum;
    if (lane==0) sm[w]=mx;
    __syncthreads();
    if (tid==0){
        float t=sm[0];
#pragma unroll
        for (int j=1;j<8;j++) t=fmaxf(t,sm[j]);
        smx=t;
    }
    __syncthreads();
    float bmax=smx, sum=0.f;
#pragma unroll
    for (int i=0;i<4;i++){ vv[i]=__expf(vv[i]-bmax); sum+=vv[i]; }
#pragma unroll
    for (int off=16; off; off>>=1) sum += __shfl_xor_sync(0xffffffffu, sum, off);
    if (lane==0) ss[w]=sum;
    __syncthreads();
    if (tid==0){
        float t=0.f;
#pragma unroll
        for (int j=0;j<8;j++) t+=ss[j];
        ssum=t;
    }
    __syncthreads();
    float inv = 1.0f/ssum;
#pragma unroll
    for (int i=0;i<4;i++) sr[tid+i*256] = vv[i]*inv;
}

__global__ void __launch_bounds__(256) router_kernel(
    const float* __restrict__ xn2, const float* __restrict__ wr,
    const float* __restrict__ br, float* __restrict__ logits)
{
    int t = blockIdx.x;
    int w = threadIdx.x>>5, lane = threadIdx.x&31;
    const float* xr = xn2 + (ll)t*Dc;
    float s=0.f;
    for (int kk=lane; kk<Dc; kk+=32) s += xr[kk]*wr[kk*Ec + w];
#pragma unroll
    for (int off=16; off; off>>=1) s += __shfl_xor_sync(0xffffffffu, s, off);
    if (lane==0) logits[t*Ec + w] = s + br[w];
}

__global__ void zero_cnt_kernel(int* cnt){ if (threadIdx.x < Ec) cnt[threadIdx.x]=0; }

__global__ void __launch_bounds__(256) topk_kernel(
    const float* __restrict__ logits, int* __restrict__ cnt,
    int* __restrict__ etok, int* __restrict__ slot, float* __restrict__ wgt)
{
    int t = blockIdx.x*blockDim.x + threadIdx.x;
    if (t >= TOK) return;
    float l[Ec];
#pragma unroll
    for (int e=0;e<Ec;e++) l[e]=logits[t*Ec+e];
    int i0=0;
#pragma unroll
    for (int e=1;e<Ec;e++) if (l[e] > l[i0]) i0=e;
    int i1=-1;
#pragma unroll
    for (int e=0;e<Ec;e++){ if (e==i0) continue; if (i1<0 || l[e]>l[i1]) i1=e; }
    float ex = __expf(l[i1]-l[i0]);
    float p0 = 1.0f/(1.0f+ex);
    float p1 = ex/(1.0f+ex);
    int s0 = atomicAdd(&cnt[i0], 1);
    int s1 = atomicAdd(&cnt[i1], 1);
    etok[i0*4096+s0] = t;
    etok[i1*4096+s1] = t;
    slot[t*2+0] = i0*4096+s0;
    slot[t*2+1] = i1*4096+s1;
    wgt[t*2+0] = p0;
    wgt[t*2+1] = p1;
}

__global__ void __launch_bounds__(256) combine_kernel(
    const float* __restrict__ x1, const float* __restrict__ eo,
    const int* __restrict__ slot, const float* __restrict__ wgt,
    float* __restrict__ out)
{
    int t = blockIdx.x;
    int s0=slot[t*2], s1=slot[t*2+1];
    float w0=wgt[t*2], w1=wgt[t*2+1];
    const float* e0 = eo + (ll)s0*Dc;
    const float* e1 = eo + (ll)s1*Dc;
    const float* xr = x1 + (ll)t*Dc;
    float* orow = out + (ll)t*Dc;
#pragma unroll
    for (int i=0;i<4;i++){
        int c = threadIdx.x + i*256;
        orow[c] = xr[c] + w0*e0[c] + w1*e1[c];
    }
}

extern "C" void kernel_launch(void* const* d_in, const int* in_sizes, int n_in,
                              void* d_out, int out_size)
{
    (void)in_sizes; (void)n_in; (void)out_size;
    const float* x     = (const float*)d_in[0];
    const int*   mask  = (const int*)  d_in[1];
    const float* ln1_g = (const float*)d_in[2];
    const float* ln1_b = (const float*)d_in[3];
    const float* ln2_g = (const float*)d_in[4];
    const float* ln2_b = (const float*)d_in[5];
    const float* wq    = (const float*)d_in[6];
    const float* bq    = (const float*)d_in[7];
    const float* wk    = (const float*)d_in[8];
    const float* bk    = (const float*)d_in[9];
    const float* wv    = (const float*)d_in[10];
    const float* bv    = (const float*)d_in[11];
    const float* wo    = (const float*)d_in[12];
    const float* bo    = (const float*)d_in[13];
    const float* w_rt  = (const float*)d_in[14];
    const float* b_rt  = (const float*)d_in[15];
    const float* w1    = (const float*)d_in[16];
    const float* b1    = (const float*)d_in[17];
    const float* w2    = (const float*)d_in[18];
    const float* b2    = (const float*)d_in[19];
    float* out = (float*)d_out;

    // resolve scratch symbols (host-side, capture-safe: not a stream op)
    void *pPool=nullptr, *pX1=nullptr, *pXn2=nullptr, *pLog=nullptr,
         *pWgt=nullptr, *pCnt=nullptr, *pEtok=nullptr, *pSlot=nullptr;
    cudaGetSymbolAddress(&pPool, g_pool);
    cudaGetSymbolAddress(&pX1,   g_x1);
    cudaGetSymbolAddress(&pXn2,  g_xn2);
    cudaGetSymbolAddress(&pLog,  g_logits);
    cudaGetSymbolAddress(&pWgt,  g_wgt);
    cudaGetSymbolAddress(&pCnt,  g_cnt);
    cudaGetSymbolAddress(&pEtok, g_etok);
    cudaGetSymbolAddress(&pSlot, g_slot);

    float* pool   = (float*)pPool;
    float* x1     = (float*)pX1;
    float* xn2    = (float*)pXn2;
    float* logits = (float*)pLog;
    float* wgt    = (float*)pWgt;
    int*   cnt    = (int*)pCnt;
    int*   etok   = (int*)pEtok;
    int*   slot   = (int*)pSlot;

    // Phase A layout in pool
    float* xn     = pool + 0*TD;
    float* q      = pool + 1*TD;
    float* k      = pool + 2*TD;
    float* v      = pool + 3*TD;
    float* ao     = pool + 4*TD;
    float* scores = pool + 5*TD;          // SC_SZ elems
    // Phase B layout in pool (overlaps Phase A; Phase A is dead by then)
    float* h      = pool;                  // E*4096*FF elems
    float* eo     = pool + (ll)Ec*4096*FFc;

    ln_kernel<<<TOK, 256>>>(x, ln1_g, ln1_b, xn);

    gemm_tf32<128,0,0,false><<<dim3(Dc/128, TOK/128, 1), 256>>>(
        xn, Dc, 0, 0, wq, Dc, 0, 0, q, Dc, 0, 0,
        bq, 0, nullptr, 1.0f, TOK, Dc, Dc, 1, nullptr, nullptr);
    gemm_tf32<128,0,0,false><<<dim3(Dc/128, TOK/128, 1), 256>>>(
        xn, Dc, 0, 0, wk, Dc, 0, 0, k, Dc, 0, 0,
        bk, 0, nullptr, 1.0f, TOK, Dc, Dc, 1, nullptr, nullptr);
    gemm_tf32<128,0,0,false><<<dim3(Dc/128, TOK/128, 1), 256>>>(
        xn, Dc, 0, 0, wv, Dc, 0, 0, v, Dc, 0, 0,
        bv, 0, nullptr, 1.0f, TOK, Dc, Dc, 1, nullptr, nullptr);

    // scores = QK^T * 1/8 : z = b*16+h, M=N=1024, K=64
    gemm_tf32<128,1,0,false><<<dim3(Sc/128, Sc/128, Bc*Hc), 256>>>(
        q, Dc, (ll)Sc*Dc, DHc,
        k, Dc, (ll)Sc*Dc, DHc,
        scores, Sc, (ll)Hc*Sc*Sc, (ll)Sc*Sc,
        nullptr, 0, nullptr, 0.125f, Sc, Sc, DHc, Hc, nullptr, nullptr);

    softmax_kernel<<<Bc*Hc*Sc, 256>>>(scores, mask);

    // AV: probs @ V, M=1024, N=64, K=1024
    gemm_tf32<64,0,0,false><<<dim3(1, Sc/128, Bc*Hc), 256>>>(
        scores, Sc, (ll)Hc*Sc*Sc, (ll)Sc*Sc,
        v, Dc, (ll)Sc*Dc, DHc,
        ao, Dc, (ll)Sc*Dc, DHc,
        nullptr, 0, nullptr, 1.0f, Sc, DHc, Sc, Hc, nullptr, nullptr);

    // x1 = x + ao @ wo + bo
    gemm_tf32<128,0,0,false><<<dim3(Dc/128, TOK/128, 1), 256>>>(
        ao, Dc, 0, 0, wo, Dc, 0, 0, x1, Dc, 0, 0,
        bo, 0, x, 1.0f, TOK, Dc, Dc, 1, nullptr, nullptr);

    ln_kernel<<<TOK, 256>>>(x1, ln2_g, ln2_b, xn2);

    router_kernel<<<TOK, 256>>>(xn2, w_rt, b_rt, logits);
    zero_cnt_kernel<<<1, 32>>>(cnt);
    topk_kernel<<<TOK/256, 256>>>(logits, cnt, etok, slot, wgt);

    // expert GEMM1: h[slot] = GELU(xn2[gathered] @ w1[e] + b1[e])
    gemm_tf32<128,0,1,true><<<dim3(FFc/128, 4096/128, Ec), 256>>>(
        xn2, Dc, 0, 0,
        w1, FFc, (ll)Dc*FFc, 0,
        h, FFc, (ll)4096*FFc, 0,
        b1, FFc, nullptr, 1.0f, 4096, FFc, Dc, 1, etok, cnt);

    // expert GEMM2: eo[slot] = h[slot] @ w2[e] + b2[e]
    gemm_tf32<128,0,0,false><<<dim3(Dc/128, 4096/128, Ec), 256>>>(
        h, FFc, (ll)4096*FFc, 0,
        w2, Dc, (ll)FFc*Dc, 0,
        eo, Dc, (ll)4096*Dc, 0,
        b2, Dc, nullptr, 1.0f, 4096, Dc, FFc, 1, nullptr, cnt);

    combine_kernel<<<TOK, 256>>>(x1, eo, slot, wgt, out);
}

// round 4
// speedup vs baseline: 1.3338x; 1.3338x over previous
#include <cuda_runtime.h>
#include <math.h>
#include <stdint.h>

typedef long long ll;
#define DI __device__ __forceinline__

constexpr int Bc=4, Sc=1024, Dc=1024, Hc=16, DHc=64, Ec=8, FFc=4096;
constexpr int TOK = Bc*Sc;                 // 4096
constexpr ll TD   = (ll)TOK*Dc;            // 4,194,304 elems (16MB)
constexpr ll SC_SZ= (ll)Bc*Hc*Sc*Sc;       // 67,108,864 elems (256MB)

// ---- phase-overlapped scratch pool + persistents ----
// Phase A (attention): [xn | q | k | v | ao | scores] = 5*TD + SC_SZ = 336MB
// Phase B (MoE):       [h (512MB) | eo (128MB)]       = 640MB
constexpr ll POOL_ELEMS = (ll)Ec*4096*FFc + (ll)Ec*4096*Dc;
__device__ float g_pool[POOL_ELEMS];
__device__ float g_x1 [TD];
__device__ float g_xn2[TD];
__device__ float g_logits[TOK*Ec];
__device__ float g_wgt[TOK*2];
__device__ int   g_cnt[Ec];
__device__ int   g_etok[Ec*4096];
__device__ int   g_slot[TOK*2];

DI uint32_t smaddr(const void* p){ return (uint32_t)__cvta_generic_to_shared(p); }
DI void cp16(uint32_t dst, const void* src){
    asm volatile("cp.async.ca.shared.global [%0], [%1], 16;" :: "r"(dst), "l"(src));
}
DI void cp_commit(){ asm volatile("cp.async.commit_group;" ::: "memory"); }
template<int N> DI void cp_wait(){ asm volatile("cp.async.wait_group %0;" :: "n"(N) : "memory"); }

DI void mma_tf32(float* c, const unsigned* a, const unsigned* b){
    asm volatile("mma.sync.aligned.m16n8k8.row.col.f32.tf32.tf32.f32 "
        "{%0,%1,%2,%3}, {%4,%5,%6,%7}, {%8,%9}, {%0,%1,%2,%3};"
        : "+f"(c[0]),"+f"(c[1]),"+f"(c[2]),"+f"(c[3])
        : "r"(a[0]),"r"(a[1]),"r"(a[2]),"r"(a[3]),"r"(b[0]),"r"(b[1]));
}

DI float gelu_exact(float x){ return 0.5f*x*(1.0f+erff(x*0.70710678118654752440f)); }

// C[z] = epi(A[z]@B[z]*scale + bias, residual)
// BLAYOUT 0: B is [K,N] row-major. 1: B is [N,K] row-major (B^T).
// EPI 1: GELU epilogue. GATHER: A rows from per-z gather list. counts bounds M.
// 2-stage cp.async pipeline; tf32 via raw-bit truncation (HW uses top 19 bits).
template <int BN, int BLAYOUT, int EPI, bool GATHER>
__global__ void __launch_bounds__(256) gemm_tf32(
    const float* __restrict__ A, int lda, ll sAb, ll sAh,
    const float* __restrict__ B, int ldb, ll sBb, ll sBh,
    float* __restrict__ C, int ldc, ll sCb, ll sCh,
    const float* __restrict__ bias, ll biasStride,
    const float* __restrict__ residual, float scale,
    int M, int N, int K, int nH,
    const int* __restrict__ gather, const int* __restrict__ counts)
{
    constexpr int BM=128, BK=16;
    constexpr int LDA_S = BK+4;
    constexpr int LDB_S = (BLAYOUT==0) ? (BN+8) : (BK+4);
    constexpr int B_ELEMS = (BLAYOUT==0) ? (BK*LDB_S) : (BN*LDB_S);
    constexpr int HALF_BN = BN/2;
    constexpr int NI = HALF_BN/8;
    constexpr int BIT = BN/64;

    __shared__ float As[2][BM*LDA_S];
    __shared__ float Bs[2][B_ELEMS];

    const int z = blockIdx.z;
    const int bb = z/nH, hh = z%nH;
    const float* Ab = A + bb*sAb + hh*sAh;
    const float* Bp = B + bb*sBb + hh*sBh;

    const int Meff = counts ? counts[z] : M;
    const int m0 = blockIdx.y*BM;
    if (m0 >= Meff) return;
    const int n0 = blockIdx.x*BN;

    const int tid = threadIdx.x;
    const int lane = tid&31, warp = tid>>5;
    const int wm = warp&3, wn = warp>>2;

    const int* grows = GATHER ? (gather + z*4096) : nullptr;

    // ---- per-thread staging assignments ----
    const float* asrc[2];
    uint32_t adst[2][2];
#pragma unroll
    for (int it=0; it<2; it++){
        int idx = tid + it*256;
        int r = idx>>2, c4 = (idx&3)*4;
        int m = m0 + r;
        ll srow;
        if (GATHER){ int mm = (m < Meff) ? m : (Meff-1); srow = grows[mm]; }
        else srow = m;
        asrc[it] = Ab + srow*(ll)lda + c4;
#pragma unroll
        for (int s=0;s<2;s++) adst[it][s] = smaddr(&As[s][r*LDA_S + c4]);
    }
    const float* bsrc[BIT];
    uint32_t bdst[BIT][2];
#pragma unroll
    for (int it=0; it<BIT; it++){
        int idx = tid + it*256;
        int r, c4;
        if (BLAYOUT==0){ r = idx/(BN/4); c4 = (idx%(BN/4))*4; }
        else           { r = idx>>2;     c4 = (idx&3)*4; }
        if (BLAYOUT==0) bsrc[it] = Bp + (ll)r*ldb + n0 + c4;
        else            bsrc[it] = Bp + (ll)(n0+r)*ldb + c4;
#pragma unroll
        for (int s=0;s<2;s++) bdst[it][s] = smaddr(&Bs[s][r*LDB_S + c4]);
    }

    float acc[2][NI][4];
#pragma unroll
    for (int mi=0;mi<2;mi++)
#pragma unroll
    for (int ni=0;ni<NI;ni++)
#pragma unroll
    for (int j=0;j<4;j++) acc[mi][ni][j]=0.0f;

    const int r0 = lane>>2, cc = lane&3;
    const int KT = K / BK;

    // ---- prologue: stage 0 ----
    {
#pragma unroll
        for (int it=0; it<2; it++) cp16(adst[it][0], asrc[it]);
#pragma unroll
        for (int it=0; it<BIT; it++) cp16(bdst[it][0], bsrc[it]);
        cp_commit();
    }

    for (int kt=0; kt<KT; kt++){
        // issue next stage (target buffer was released by the trailing sync)
        if (kt+1 < KT){
            int s = (kt+1)&1;
            int k0 = (kt+1)*BK;
            ll boff = (BLAYOUT==0) ? (ll)k0*ldb : (ll)k0;
#pragma unroll
            for (int it=0; it<2; it++) cp16(adst[it][s], asrc[it] + k0);
#pragma unroll
            for (int it=0; it<BIT; it++) cp16(bdst[it][s], bsrc[it] + boff);
            cp_commit();
            cp_wait<1>();
        } else {
            cp_wait<0>();
        }
        __syncthreads();

        const int cur = kt&1;
        const float* Asp = As[cur];
        const float* Bsp = Bs[cur];
#pragma unroll
        for (int kk=0; kk<BK; kk+=8){
            unsigned a[2][4], b[NI][2];
#pragma unroll
            for (int mi=0;mi<2;mi++){
                int rb = wm*32 + mi*16;
                a[mi][0]=__float_as_uint(Asp[(rb+r0  )*LDA_S + kk+cc  ]);
                a[mi][1]=__float_as_uint(Asp[(rb+r0+8)*LDA_S + kk+cc  ]);
                a[mi][2]=__float_as_uint(Asp[(rb+r0  )*LDA_S + kk+cc+4]);
                a[mi][3]=__float_as_uint(Asp[(rb+r0+8)*LDA_S + kk+cc+4]);
            }
#pragma unroll
            for (int ni=0;ni<NI;ni++){
                int nb = wn*HALF_BN + ni*8 + r0;
                if (BLAYOUT==0){
                    b[ni][0]=__float_as_uint(Bsp[(kk+cc  )*LDB_S + nb]);
                    b[ni][1]=__float_as_uint(Bsp[(kk+cc+4)*LDB_S + nb]);
                } else {
                    b[ni][0]=__float_as_uint(Bsp[nb*LDB_S + kk+cc  ]);
                    b[ni][1]=__float_as_uint(Bsp[nb*LDB_S + kk+cc+4]);
                }
            }
#pragma unroll
            for (int mi=0;mi<2;mi++)
#pragma unroll
            for (int ni=0;ni<NI;ni++)
                mma_tf32(acc[mi][ni], a[mi], b[ni]);
        }
        __syncthreads();
    }

    const float* biasP = bias ? (bias + z*biasStride) : nullptr;
    float* Cp = C + bb*sCb + hh*sCh;
    const float* resP = residual ? (residual + bb*sCb + hh*sCh) : nullptr;
    const int c0 = (lane&3)*2;

#pragma unroll
    for (int mi=0;mi<2;mi++)
#pragma unroll
    for (int ni=0;ni<NI;ni++)
#pragma unroll
    for (int half=0; half<2; half++){
        int row = m0 + wm*32 + mi*16 + r0 + half*8;
        int col = n0 + wn*HALF_BN + ni*8 + c0;
        float v0 = acc[mi][ni][half*2+0]*scale;
        float v1 = acc[mi][ni][half*2+1]*scale;
        if (biasP){ v0 += biasP[col]; v1 += biasP[col+1]; }
        if (EPI==1){ v0 = gelu_exact(v0); v1 = gelu_exact(v1); }
        ll ci = (ll)row*ldc + col;
        if (resP){ v0 += resP[ci]; v1 += resP[ci+1]; }
        Cp[ci]=v0; Cp[ci+1]=v1;
    }
}

__global__ void __launch_bounds__(256) ln_kernel(
    const float* __restrict__ x, const float* __restrict__ g,
    const float* __restrict__ bet, float* __restrict__ o)
{
    int row = blockIdx.x;
    const float* xr = x + (ll)row*Dc;
    float* orow = o + (ll)row*Dc;
    int tid = threadIdx.x;
    float vv[4], s=0.f, s2=0.f;
#pragma unroll
    for (int i=0;i<4;i++){ float t = xr[tid+i*256]; vv[i]=t; s+=t; s2+=t*t; }
    int lane=tid&31, w=tid>>5;
#pragma unroll
    for (int off=16; off; off>>=1){
        s  += __shfl_xor_sync(0xffffffffu, s,  off);
        s2 += __shfl_xor_sync(0xffffffffu, s2, off);
    }
    __shared__ float rs[8], rs2[8], fmu, frs;
    if (lane==0){ rs[w]=s; rs2[w]=s2; }
    __syncthreads();
    if (tid==0){
        float a=0.f, b2=0.f;
#pragma unroll
        for (int j=0;j<8;j++){ a+=rs[j]; b2+=rs2[j]; }
        float mu = a*(1.0f/Dc);
        float var = b2*(1.0f/Dc) - mu*mu;
        fmu=mu; frs=rsqrtf(var + 1e-5f);
    }
    __syncthreads();
    float mu=fmu, rstd=frs;
#pragma unroll
    for (int i=0;i<4;i++){ int c=tid+i*256; orow[c] = (vv[i]-mu)*rstd*g[c] + bet[c]; }
}

__global__ void __launch_bounds__(256) softmax_kernel(
    float* __restrict__ sc, const int* __restrict__ mask)
{
    ll row = blockIdx.x;
    int b = (int)(row >> 14);
    float* sr = sc + row*(ll)Sc;
    const int* mr = mask + (ll)b*Sc;
    int tid=threadIdx.x, lane=tid&31, w=tid>>5;
    float vv[4], mx = -1e30f;
#pragma unroll
    for (int i=0;i<4;i++){
        int c = tid+i*256;
        float val = (mr[c]!=0) ? sr[c] : -1e30f;
        vv[i]=val; mx=fmaxf(mx,val);
    }
#pragma unroll
    for (int off=16; off; off>>=1) mx = fmaxf(mx, __shfl_xor_sync(0xffffffffu, mx, off));
    __shared__ float sm[8], smx, ss[8], ssum;
    if (lane==0) sm[w]=mx;
    __syncthreads();
    if (tid==0){
        float t=sm[0];
#pragma unroll
        for (int j=1;j<8;j++) t=fmaxf(t,sm[j]);
        smx=t;
    }
    __syncthreads();
    float bmax=smx, sum=0.f;
#pragma unroll
    for (int i=0;i<4;i++){ vv[i]=__expf(vv[i]-bmax); sum+=vv[i]; }
#pragma unroll
    for (int off=16; off; off>>=1) sum += __shfl_xor_sync(0xffffffffu, sum, off);
    if (lane==0) ss[w]=sum;
    __syncthreads();
    if (tid==0){
        float t=0.f;
#pragma unroll
        for (int j=0;j<8;j++) t+=ss[j];
        ssum=t;
    }
    __syncthreads();
    float inv = 1.0f/ssum;
#pragma unroll
    for (int i=0;i<4;i++) sr[tid+i*256] = vv[i]*inv;
}

__global__ void __launch_bounds__(256) router_kernel(
    const float* __restrict__ xn2, const float* __restrict__ wr,
    const float* __restrict__ br, float* __restrict__ logits)
{
    int t = blockIdx.x;
    int w = threadIdx.x>>5, lane = threadIdx.x&31;
    const float* xr = xn2 + (ll)t*Dc;
    float s=0.f;
    for (int kk=lane; kk<Dc; kk+=32) s += xr[kk]*wr[kk*Ec + w];
#pragma unroll
    for (int off=16; off; off>>=1) s += __shfl_xor_sync(0xffffffffu, s, off);
    if (lane==0) logits[t*Ec + w] = s + br[w];
}

__global__ void zero_cnt_kernel(int* cnt){ if (threadIdx.x < Ec) cnt[threadIdx.x]=0; }

__global__ void __launch_bounds__(256) topk_kernel(
    const float* __restrict__ logits, int* __restrict__ cnt,
    int* __restrict__ etok, int* __restrict__ slot, float* __restrict__ wgt)
{
    int t = blockIdx.x*blockDim.x + threadIdx.x;
    if (t >= TOK) return;
    float l[Ec];
#pragma unroll
    for (int e=0;e<Ec;e++) l[e]=logits[t*Ec+e];
    int i0=0;
#pragma unroll
    for (int e=1;e<Ec;e++) if (l[e] > l[i0]) i0=e;
    int i1=-1;
#pragma unroll
    for (int e=0;e<Ec;e++){ if (e==i0) continue; if (i1<0 || l[e]>l[i1]) i1=e; }
    float ex = __expf(l[i1]-l[i0]);
    float p0 = 1.0f/(1.0f+ex);
    float p1 = ex/(1.0f+ex);
    int s0 = atomicAdd(&cnt[i0], 1);
    int s1 = atomicAdd(&cnt[i1], 1);
    etok[i0*4096+s0] = t;
    etok[i1*4096+s1] = t;
    slot[t*2+0] = i0*4096+s0;
    slot[t*2+1] = i1*4096+s1;
    wgt[t*2+0] = p0;
    wgt[t*2+1] = p1;
}

__global__ void __launch_bounds__(256) combine_kernel(
    const float* __restrict__ x1, const float* __restrict__ eo,
    const int* __restrict__ slot, const float* __restrict__ wgt,
    float* __restrict__ out)
{
    int t = blockIdx.x;
    int s0=slot[t*2], s1=slot[t*2+1];
    float w0=wgt[t*2], w1=wgt[t*2+1];
    const float* e0 = eo + (ll)s0*Dc;
    const float* e1 = eo + (ll)s1*Dc;
    const float* xr = x1 + (ll)t*Dc;
    float* orow = out + (ll)t*Dc;
#pragma unroll
    for (int i=0;i<4;i++){
        int c = threadIdx.x + i*256;
        orow[c] = xr[c] + w0*e0[c] + w1*e1[c];
    }
}

extern "C" void kernel_launch(void* const* d_in, const int* in_sizes, int n_in,
                              void* d_out, int out_size)
{
    (void)in_sizes; (void)n_in; (void)out_size;
    const float* x     = (const float*)d_in[0];
    const int*   mask  = (const int*)  d_in[1];
    const float* ln1_g = (const float*)d_in[2];
    const float* ln1_b = (const float*)d_in[3];
    const float* ln2_g = (const float*)d_in[4];
    const float* ln2_b = (const float*)d_in[5];
    const float* wq    = (const float*)d_in[6];
    const float* bq    = (const float*)d_in[7];
    const float* wk    = (const float*)d_in[8];
    const float* bk    = (const float*)d_in[9];
    const float* wv    = (const float*)d_in[10];
    const float* bv    = (const float*)d_in[11];
    const float* wo    = (const float*)d_in[12];
    const float* bo    = (const float*)d_in[13];
    const float* w_rt  = (const float*)d_in[14];
    const float* b_rt  = (const float*)d_in[15];
    const float* w1    = (const float*)d_in[16];
    const float* b1    = (const float*)d_in[17];
    const float* w2    = (const float*)d_in[18];
    const float* b2    = (const float*)d_in[19];
    float* out = (float*)d_out;

    void *pPool=nullptr, *pX1=nullptr, *pXn2=nullptr, *pLog=nullptr,
         *pWgt=nullptr, *pCnt=nullptr, *pEtok=nullptr, *pSlot=nullptr;
    cudaGetSymbolAddress(&pPool, g_pool);
    cudaGetSymbolAddress(&pX1,   g_x1);
    cudaGetSymbolAddress(&pXn2,  g_xn2);
    cudaGetSymbolAddress(&pLog,  g_logits);
    cudaGetSymbolAddress(&pWgt,  g_wgt);
    cudaGetSymbolAddress(&pCnt,  g_cnt);
    cudaGetSymbolAddress(&pEtok, g_etok);
    cudaGetSymbolAddress(&pSlot, g_slot);

    float* pool   = (float*)pPool;
    float* x1     = (float*)pX1;
    float* xn2    = (float*)pXn2;
    float* logits = (float*)pLog;
    float* wgt    = (float*)pWgt;
    int*   cnt    = (int*)pCnt;
    int*   etok   = (int*)pEtok;
    int*   slot   = (int*)pSlot;

    float* xn     = pool + 0*TD;
    float* q      = pool + 1*TD;
    float* k      = pool + 2*TD;
    float* v      = pool + 3*TD;
    float* ao     = pool + 4*TD;
    float* scores = pool + 5*TD;
    float* h      = pool;
    float* eo     = pool + (ll)Ec*4096*FFc;

    ln_kernel<<<TOK, 256>>>(x, ln1_g, ln1_b, xn);

    gemm_tf32<128,0,0,false><<<dim3(Dc/128, TOK/128, 1), 256>>>(
        xn, Dc, 0, 0, wq, Dc, 0, 0, q, Dc, 0, 0,
        bq, 0, nullptr, 1.0f, TOK, Dc, Dc, 1, nullptr, nullptr);
    gemm_tf32<128,0,0,false><<<dim3(Dc/128, TOK/128, 1), 256>>>(
        xn, Dc, 0, 0, wk, Dc, 0, 0, k, Dc, 0, 0,
        bk, 0, nullptr, 1.0f, TOK, Dc, Dc, 1, nullptr, nullptr);
    gemm_tf32<128,0,0,false><<<dim3(Dc/128, TOK/128, 1), 256>>>(
        xn, Dc, 0, 0, wv, Dc, 0, 0, v, Dc, 0, 0,
        bv, 0, nullptr, 1.0f, TOK, Dc, Dc, 1, nullptr, nullptr);

    // scores = QK^T * 1/8
    gemm_tf32<128,1,0,false><<<dim3(Sc/128, Sc/128, Bc*Hc), 256>>>(
        q, Dc, (ll)Sc*Dc, DHc,
        k, Dc, (ll)Sc*Dc, DHc,
        scores, Sc, (ll)Hc*Sc*Sc, (ll)Sc*Sc,
        nullptr, 0, nullptr, 0.125f, Sc, Sc, DHc, Hc, nullptr, nullptr);

    softmax_kernel<<<Bc*Hc*Sc, 256>>>(scores, mask);

    // AV: probs @ V
    gemm_tf32<64,0,0,false><<<dim3(1, Sc/128, Bc*Hc), 256>>>(
        scores, Sc, (ll)Hc*Sc*Sc, (ll)Sc*Sc,
        v, Dc, (ll)Sc*Dc, DHc,
        ao, Dc, (ll)Sc*Dc, DHc,
        nullptr, 0, nullptr, 1.0f, Sc, DHc, Sc, Hc, nullptr, nullptr);

    // x1 = x + ao @ wo + bo
    gemm_tf32<128,0,0,false><<<dim3(Dc/128, TOK/128, 1), 256>>>(
        ao, Dc, 0, 0, wo, Dc, 0, 0, x1, Dc, 0, 0,
        bo, 0, x, 1.0f, TOK, Dc, Dc, 1, nullptr, nullptr);

    ln_kernel<<<TOK, 256>>>(x1, ln2_g, ln2_b, xn2);

    router_kernel<<<TOK, 256>>>(xn2, w_rt, b_rt, logits);
    zero_cnt_kernel<<<1, 32>>>(cnt);
    topk_kernel<<<TOK/256, 256>>>(logits, cnt, etok, slot, wgt);

    // expert GEMM1: h[slot] = GELU(xn2[gathered] @ w1[e] + b1[e])
    gemm_tf32<128,0,1,true><<<dim3(FFc/128, 4096/128, Ec), 256>>>(
        xn2, Dc, 0, 0,
        w1, FFc, (ll)Dc*FFc, 0,
        h, FFc, (ll)4096*FFc, 0,
        b1, FFc, nullptr, 1.0f, 4096, FFc, Dc, 1, etok, cnt);

    // expert GEMM2: eo[slot] = h[slot] @ w2[e] + b2[e]
    gemm_tf32<128,0,0,false><<<dim3(Dc/128, 4096/128, Ec), 256>>>(
        h, FFc, (ll)4096*FFc, 0,
        w2, Dc, (ll)FFc*Dc, 0,
        eo, Dc, (ll)4096*Dc, 0,
        b2, Dc, nullptr, 1.0f, 4096, Dc, FFc, 1, nullptr, cnt);

    combine_kernel<<<TOK, 256>>>(x1, eo, slot, wgt, out);
}